// round 13
// baseline (speedup 1.0000x reference)
#include <cuda_runtime.h>
#include <cuda_bf16.h>
#include <cstdint>

// Problem constants
#define BSZ   2048
#define K1    9408     // 3*56*56
#define N1    1024     // PROJ_OUT
#define HD    2048     // HIDDEN_DIM
#define NC    65       // N_CLASSES
#define WLD   3072     // W_fc leading dim
#define KSPLIT 16      // s1 split-K slices

// ---------------------------------------------------------------------------
// PTX helpers (baseline ISA only)
// ---------------------------------------------------------------------------
__device__ __forceinline__ uint32_t smem_to_u32(const void* p) {
    uint32_t a;
    asm("{ .reg .u64 t; cvta.to.shared.u64 t, %1; cvt.u32.u64 %0, t; }" : "=r"(a) : "l"(p));
    return a;
}
#define CP_ASYNC_16(dst, src) \
    asm volatile("cp.async.cg.shared.global [%0], [%1], 16;" :: "r"(dst), "l"(src))
#define CP_ASYNC_COMMIT() asm volatile("cp.async.commit_group;" ::: "memory")
#define CP_ASYNC_WAIT(n)  asm volatile("cp.async.wait_group %0;" :: "n"(n) : "memory")

#define LDSM_X4(r0,r1,r2,r3,addr) \
    asm volatile("ldmatrix.sync.aligned.m8n8.x4.shared.b16 {%0,%1,%2,%3}, [%4];" \
        : "=r"(r0),"=r"(r1),"=r"(r2),"=r"(r3) : "r"(addr))

// FP8 e4m3 MMA, K=32 per instruction. Fragment byte layout identical to
// bf16 m16n8k16 fragments -> same ldmatrix staging works.
#define MMA_FP8(c0,c1,c2,c3,a0,a1,a2,a3,b0,b1) \
    asm volatile("mma.sync.aligned.m16n8k32.row.col.f32.e4m3.e4m3.f32 " \
        "{%0,%1,%2,%3}, {%4,%5,%6,%7}, {%8,%9}, {%0,%1,%2,%3};" \
        : "+f"(c0),"+f"(c1),"+f"(c2),"+f"(c3) \
        : "r"(a0),"r"(a1),"r"(a2),"r"(a3), "r"(b0),"r"(b1))

// pack 4 floats -> 4 e4m3 bytes (f0 in byte 0)
__device__ __forceinline__ uint32_t pack_e4m3(float f0, float f1, float f2, float f3) {
    uint32_t d;
    asm("{\n\t.reg .b16 lo, hi;\n\t"
        "cvt.rn.satfinite.e4m3x2.f32 lo, %2, %1;\n\t"
        "cvt.rn.satfinite.e4m3x2.f32 hi, %4, %3;\n\t"
        "mov.b32 %0, {lo, hi};\n\t}"
        : "=r"(d) : "f"(f0), "f"(f1), "f"(f2), "f"(f3));
    return d;
}

// ---------------------------------------------------------------------------
// Scratch
// ---------------------------------------------------------------------------
#define BSCALE 64.0f                  // 2^6: lift W_proj out of e4m3 subnormals
#define BSCALE_INV 0.015625f
__device__ uint8_t g_Bf8[(size_t)N1 * K1];            // W_proj*64 in e4m3 (9.6 MB)
__device__ __nv_bfloat16 g_Dbf[(size_t)2 * BSZ * N1]; // K-half partials bf16 (8.4 MB)
__device__ float g_partial[128 * N1];                 // per row-block column sums
__device__ float g_T[NC];
__device__ float g_s1part[KSPLIT * BSZ * NC];

// ---------------------------------------------------------------------------
// fp32 -> e4m3 conversion for B (W_proj), scaled by 64.
// ---------------------------------------------------------------------------
#define NB4 ((N1 * K1) / 4)
__global__ void convertB_kernel(const float* __restrict__ srcB)
{
    int i = blockIdx.x * blockDim.x + threadIdx.x;
    const int stride = gridDim.x * blockDim.x;
    for (; i < NB4; i += stride) {
        float4 f = ((const float4*)srcB)[i];
        ((uint32_t*)g_Bf8)[i] = pack_e4m3(BSCALE * f.x, BSCALE * f.y,
                                          BSCALE * f.z, BSCALE * f.w);
    }
}

// ---------------------------------------------------------------------------
// GEMM1 fused fp8: CTA tile 128M x 256N, K split in 2 halves (grid 128).
// A read fp32 from z2, cvt->e4m3 in regs, 2-buffer smem ring. B e4m3 via
// cp.async 3-stage ring. 16 warps, warp tile 32x64, BK=64 (2 x k32 MMA).
// Epilogue stores raw bf16 partial tiles (relu applied after K-halves sum).
// ---------------------------------------------------------------------------
#define ROWB       80                  // 64 fp8 bytes + 16B pad (ldmatrix-safe)
#define A_TILE     (128 * ROWB)        // 10240
#define B_TILE     (256 * ROWB)        // 20480
#define A_OFF      0                   // A ring: 2 x A_TILE
#define B_OFF      (2 * A_TILE)        // B ring: 3 x B_TILE
#define G1_SMEM    (B_OFF + 3 * B_TILE)   // 81920

__global__ __launch_bounds__(512, 1) void gemm1_tc(
    const float* __restrict__ Ag, const uint8_t* __restrict__ Bg)
{
    extern __shared__ char smem[];
    const uint32_t sb = smem_to_u32(smem);
    const int tid  = threadIdx.x;
    const int lane = tid & 31;
    const int warp = tid >> 5;         // 0..15
    const int wm   = warp >> 2;        // 0..3  (M 32-row strip)
    const int wn   = warp & 3;         // 0..3  (N 64-col strip)
    const int mtile = blockIdx.x & 15;
    const int rest  = blockIdx.x >> 4;
    const int ntile = rest & 3;
    const int khalf = rest >> 2;
    const int row0 = mtile * 128;
    const int col0 = ntile * 256;
    const int kbase = khalf ? 4736 : 0;        // 74*64
    const int iters = khalf ? 73 : 74;

    // B stage loader: 256 rows x 4 chunks of 16B = 1024 -> 2/thread
    auto load_B = [&](int buf, int k0) {
        const uint32_t sB = sb + B_OFF + buf * B_TILE;
        #pragma unroll
        for (int i = 0; i < 2; i++) {
            const int v = tid + i * 512;     // 0..1023
            const int r = v >> 2, c = v & 3;
            CP_ASYNC_16(sB + r * ROWB + c * 16,
                        Bg + (size_t)(col0 + r) * K1 + k0 + c * 16);
        }
    };

    // A: 128 rows x 64 fp32 per stage = 2048 float4 -> 4/thread
    float4 pre[4];
    auto ldg_A = [&](int k0) {
        #pragma unroll
        for (int i = 0; i < 4; i++) {
            const int v = tid + i * 512;
            const int r = v >> 4, c = v & 15;
            pre[i] = *(const float4*)(Ag + (size_t)(row0 + r) * K1 + k0 + c * 4);
        }
    };
    auto sts_A = [&](int buf) {
        #pragma unroll
        for (int i = 0; i < 4; i++) {
            const int v = tid + i * 512;
            const int r = v >> 4, c = v & 15;
            *(uint32_t*)(smem + A_OFF + buf * A_TILE + r * ROWB + c * 4) =
                pack_e4m3(pre[i].x, pre[i].y, pre[i].z, pre[i].w);
        }
    };

    float acc[2][8][4];
    #pragma unroll
    for (int mt = 0; mt < 2; mt++)
        #pragma unroll
        for (int nt = 0; nt < 8; nt++)
            #pragma unroll
            for (int q = 0; q < 4; q++) acc[mt][nt][q] = 0.f;

    // Prologue
    ldg_A(kbase);
    load_B(0, kbase);      CP_ASYNC_COMMIT();
    load_B(1, kbase + 64); CP_ASYNC_COMMIT();
    sts_A(0);
    ldg_A(kbase + 64);
    CP_ASYNC_WAIT(1);
    __syncthreads();

    const int lrow = lane & 15;
    const int lseg = lane >> 4;

    int bbuf = 0;
    #pragma unroll 1
    for (int it = 0; it < iters; it++) {
        const uint32_t sa = sb + A_OFF + (it & 1) * A_TILE;
        const uint32_t sB = sb + B_OFF + bbuf * B_TILE;

        if (it + 2 < iters) {
            int nb = bbuf + 2; if (nb >= 3) nb -= 3;
            load_B(nb, kbase + (it + 2) * 64);
        }
        CP_ASYNC_COMMIT();

        #pragma unroll
        for (int ks = 0; ks < 2; ks++) {       // 2 x k32
            const uint32_t koff = ks * 32 + lseg * 16;
            uint32_t a[2][4];
            #pragma unroll
            for (int mt = 0; mt < 2; mt++) {
                uint32_t ad = sa + (uint32_t)(wm * 32 + mt * 16 + lrow) * ROWB + koff;
                LDSM_X4(a[mt][0], a[mt][1], a[mt][2], a[mt][3], ad);
            }
            uint32_t bfr[4][4];
            #pragma unroll
            for (int nb2 = 0; nb2 < 4; nb2++) {
                uint32_t bd = sB + (uint32_t)(wn * 64 + nb2 * 16 + lrow) * ROWB + koff;
                LDSM_X4(bfr[nb2][0], bfr[nb2][1], bfr[nb2][2], bfr[nb2][3], bd);
            }
            #pragma unroll
            for (int mt = 0; mt < 2; mt++)
                #pragma unroll
                for (int nt = 0; nt < 8; nt++) {
                    const int nb2 = nt >> 1, rs = nt & 1;
                    MMA_FP8(acc[mt][nt][0], acc[mt][nt][1], acc[mt][nt][2], acc[mt][nt][3],
                            a[mt][0], a[mt][1], a[mt][2], a[mt][3],
                            bfr[nb2][rs], bfr[nb2][rs + 2]);
                }
        }

        if (it + 1 < iters) sts_A((it + 1) & 1);
        if (it + 2 < iters) ldg_A(kbase + (it + 2) * 64);

        CP_ASYNC_WAIT(1);
        __syncthreads();
        bbuf++; if (bbuf >= 3) bbuf = 0;
    }

    // Epilogue: store raw bf16 partials (D = A_q @ (64 B_q)^T).
    {
        __nv_bfloat16* Dp = g_Dbf + (size_t)khalf * BSZ * N1;
        const int rbase = row0 + wm * 32 + (lane >> 2);
        const int cbase = col0 + wn * 64 + (lane & 3) * 2;
        #pragma unroll
        for (int mt = 0; mt < 2; mt++)
            #pragma unroll
            for (int nt = 0; nt < 8; nt++) {
                const int r = rbase + mt * 16;
                const int c = cbase + nt * 8;
                __nv_bfloat162 v0 = __floats2bfloat162_rn(acc[mt][nt][0], acc[mt][nt][1]);
                __nv_bfloat162 v1 = __floats2bfloat162_rn(acc[mt][nt][2], acc[mt][nt][3]);
                *(uint32_t*)(Dp + (size_t)r * N1 + c)       = *(uint32_t*)&v0;
                *(uint32_t*)(Dp + (size_t)(r + 8) * N1 + c) = *(uint32_t*)&v1;
            }
    }
}

// relu((D0 + D1)/64 + bias) column sums. 512 blocks x 256 thr, 16 rows each.
__global__ void relu_colsum_kernel(const float* __restrict__ bias)
{
    const int bm = blockIdx.x & 127;       // 16-row block
    const int bn = blockIdx.x >> 7;        // 256-col block
    const int c  = bn * 256 + threadIdx.x;
    const float bb = bias[c];
    const __nv_bfloat16* p0 = g_Dbf + (size_t)(bm * 16) * N1 + c;
    const __nv_bfloat16* p1 = p0 + (size_t)BSZ * N1;
    float s = 0.f;
    #pragma unroll
    for (int r = 0; r < 16; r++)
        s += fmaxf((__bfloat162float(p0[(size_t)r * N1]) +
                    __bfloat162float(p1[(size_t)r * N1])) * BSCALE_INV + bb, 0.f);
    g_partial[bm * N1 + c] = s;
}

// g_T[c] = (Σ_m g_partial[m]) . W_fc[c, HD:] + 2048*b_fc[c]
__global__ void s2_kernel(const float* __restrict__ Wfc, const float* __restrict__ bfc)
{
    __shared__ float red[1024];
    const int c = blockIdx.x, tid = threadIdx.x;
    float u = 0.f;
    #pragma unroll 8
    for (int m = 0; m < 128; m++) u += g_partial[m * N1 + tid];
    red[tid] = u * Wfc[(size_t)c * WLD + HD + tid];
    __syncthreads();
    for (int s = 512; s > 0; s >>= 1) {
        if (tid < s) red[tid] += red[tid + s];
        __syncthreads();
    }
    if (tid == 0) g_T[c] = red[0] + 2048.f * bfc[c];
}

// ---------------------------------------------------------------------------
// s1 = z1 @ W_fc[:, :HD]^T, split-K 16 slices of 128.
// ---------------------------------------------------------------------------
__global__ __launch_bounds__(256, 2) void s1_kernel(
    const float* __restrict__ A, const float* __restrict__ W)
{
    __shared__ float As[16][132];
    __shared__ float Bs[16][68];

    const int tid   = threadIdx.x;
    const int cg    = tid & 15;
    const int rg    = tid >> 4;
    const int row0  = blockIdx.x * 128;
    const int kbase = blockIdx.y * 128;

    const int lrow = tid >> 2;
    const int lq   = tid & 3;
    const float* Aptr0 = A + (size_t)(row0 + lrow) * HD + kbase + lq * 4;
    const float* Aptr1 = Aptr0 + (size_t)64 * HD;

    float acc[8][5];
    #pragma unroll
    for (int r = 0; r < 8; r++)
        #pragma unroll
        for (int j = 0; j < 5; j++) acc[r][j] = 0.f;

    for (int kk = 0; kk < 128; kk += 16) {
        __syncthreads();
        {
            float4 a0 = *(const float4*)(Aptr0 + kk);
            float4 a1 = *(const float4*)(Aptr1 + kk);
            As[lq*4+0][lrow]    = a0.x; As[lq*4+1][lrow]    = a0.y;
            As[lq*4+2][lrow]    = a0.z; As[lq*4+3][lrow]    = a0.w;
            As[lq*4+0][lrow+64] = a1.x; As[lq*4+1][lrow+64] = a1.y;
            As[lq*4+2][lrow+64] = a1.z; As[lq*4+3][lrow+64] = a1.w;
        }
        for (int f = tid; f < NC * 4; f += 256) {
            int n = f >> 2, q = f & 3;
            float4 w = *(const float4*)(W + (size_t)n * WLD + kbase + kk + q * 4);
            Bs[q*4+0][n] = w.x; Bs[q*4+1][n] = w.y;
            Bs[q*4+2][n] = w.z; Bs[q*4+3][n] = w.w;
        }
        __syncthreads();

        if (cg < 13) {
            #pragma unroll
            for (int k = 0; k < 16; k++) {
                float4 av0 = *(const float4*)(&As[k][rg*8]);
                float4 av1 = *(const float4*)(&As[k][rg*8+4]);
                float a[8] = {av0.x,av0.y,av0.z,av0.w,av1.x,av1.y,av1.z,av1.w};
                #pragma unroll
                for (int j = 0; j < 5; j++) {
                    float b = Bs[k][cg*5 + j];
                    #pragma unroll
                    for (int r = 0; r < 8; r++)
                        acc[r][j] += a[r] * b;
                }
            }
        }
    }

    if (cg < 13) {
        #pragma unroll
        for (int r = 0; r < 8; r++)
            #pragma unroll
            for (int j = 0; j < 5; j++)
                g_s1part[(size_t)blockIdx.y * (BSZ * NC)
                         + (size_t)(row0 + rg*8 + r) * NC + cg*5 + j] = acc[r][j];
    }
}

// out[i,c] = 2048 * s1[i,c] + g_T[c]
__global__ void out_kernel(float* __restrict__ out)
{
    int idx = blockIdx.x * 256 + threadIdx.x;
    if (idx < BSZ * NC) {
        int c = idx % NC;
        float s = 0.f;
        #pragma unroll
        for (int sl = 0; sl < KSPLIT; sl++) s += g_s1part[sl * (BSZ * NC) + idx];
        out[idx] = 2048.f * s + g_T[c];
    }
}

extern "C" void kernel_launch(void* const* d_in, const int* in_sizes, int n_in,
                              void* d_out, int out_size)
{
    const float* z1  = (const float*)d_in[0];
    const float* z2  = (const float*)d_in[1];
    const float* Wp  = (const float*)d_in[2];
    const float* bp  = (const float*)d_in[3];
    const float* Wfc = (const float*)d_in[4];
    const float* bfc = (const float*)d_in[5];
    float* out = (float*)d_out;

    cudaFuncSetAttribute(gemm1_tc, cudaFuncAttributeMaxDynamicSharedMemorySize, G1_SMEM);

    uint8_t* Bf8 = nullptr;
    cudaGetSymbolAddress((void**)&Bf8, g_Bf8);

    // Side stream + events, created once (no device memory involved).
    static cudaStream_t s_side = nullptr;
    static cudaEvent_t  ev_fork = nullptr, ev_join = nullptr;
    if (s_side == nullptr) {
        cudaStreamCreateWithFlags(&s_side, cudaStreamNonBlocking);
        cudaEventCreateWithFlags(&ev_fork, cudaEventDisableTiming);
        cudaEventCreateWithFlags(&ev_join, cudaEventDisableTiming);
    }

    // Fork: side stream inherits capture via event wait.
    cudaEventRecord(ev_fork, 0);
    cudaStreamWaitEvent(s_side, ev_fork, 0);

    // Side branch: s1 (fp32, SIMT) — overlaps the compute-bound gemm chain.
    s1_kernel<<<dim3(16, KSPLIT), 256, 0, s_side>>>(z1, Wfc);
    cudaEventRecord(ev_join, s_side);

    // Main branch: convert B (fp8) -> fused fp8 gemm1 -> relu+colsum -> s2
    convertB_kernel<<<592, 512>>>(Wp);
    gemm1_tc<<<128, 512, G1_SMEM>>>(z2, Bf8);
    relu_colsum_kernel<<<512, 256>>>(bp);
    s2_kernel<<<NC, 1024>>>(Wfc, bfc);

    // Join, then combine.
    cudaStreamWaitEvent(0, ev_join, 0);
    out_kernel<<<(BSZ * NC + 255) / 256, 256>>>(out);
}

// round 14
// speedup vs baseline: 1.0487x; 1.0487x over previous
#include <cuda_runtime.h>
#include <cuda_bf16.h>
#include <cstdint>

// Problem constants
#define BSZ   2048
#define K1    9408     // 3*56*56
#define N1    1024     // PROJ_OUT
#define HD    2048     // HIDDEN_DIM
#define NC    65       // N_CLASSES
#define WLD   3072     // W_fc leading dim
#define KSPLIT 16      // s1 split-K slices

// ---------------------------------------------------------------------------
// PTX helpers (baseline ISA only)
// ---------------------------------------------------------------------------
__device__ __forceinline__ uint32_t smem_to_u32(const void* p) {
    uint32_t a;
    asm("{ .reg .u64 t; cvta.to.shared.u64 t, %1; cvt.u32.u64 %0, t; }" : "=r"(a) : "l"(p));
    return a;
}
#define CP_ASYNC_16(dst, src) \
    asm volatile("cp.async.cg.shared.global [%0], [%1], 16;" :: "r"(dst), "l"(src))
#define CP_ASYNC_COMMIT() asm volatile("cp.async.commit_group;" ::: "memory")
#define CP_ASYNC_WAIT(n)  asm volatile("cp.async.wait_group %0;" :: "n"(n) : "memory")

#define LDSM_X4(r0,r1,r2,r3,addr) \
    asm volatile("ldmatrix.sync.aligned.m8n8.x4.shared.b16 {%0,%1,%2,%3}, [%4];" \
        : "=r"(r0),"=r"(r1),"=r"(r2),"=r"(r3) : "r"(addr))

#define MMA_BF16(c0,c1,c2,c3,a0,a1,a2,a3,b0,b1) \
    asm volatile("mma.sync.aligned.m16n8k16.row.col.f32.bf16.bf16.f32 " \
        "{%0,%1,%2,%3}, {%4,%5,%6,%7}, {%8,%9}, {%0,%1,%2,%3};" \
        : "+f"(c0),"+f"(c1),"+f"(c2),"+f"(c3) \
        : "r"(a0),"r"(a1),"r"(a2),"r"(a3), "r"(b0),"r"(b1))

// ---------------------------------------------------------------------------
// Scratch
// ---------------------------------------------------------------------------
__device__ __nv_bfloat16 g_Bbf[(size_t)N1 * K1];      // W_proj bf16 (19.3 MB)
__device__ __nv_bfloat16 g_Dbf[(size_t)4 * BSZ * N1]; // stream-K partial slots (16.8 MB)
__device__ float g_partial[128 * N1];                 // per row-block column sums
__device__ float g_T[NC];
__device__ float g_s1part[KSPLIT * BSZ * NC];

// ---------------------------------------------------------------------------
// fp32 -> bf16 conversion for B (W_proj).
// ---------------------------------------------------------------------------
#define NB4 ((N1 * K1) / 4)
__global__ void convertB_kernel(const float* __restrict__ srcB)
{
    int i = blockIdx.x * blockDim.x + threadIdx.x;
    const int stride = gridDim.x * blockDim.x;
    for (; i < NB4; i += stride) {
        float4 f = ((const float4*)srcB)[i];
        __nv_bfloat162 lo = __floats2bfloat162_rn(f.x, f.y);
        __nv_bfloat162 hi = __floats2bfloat162_rn(f.z, f.w);
        uint2 v;
        v.x = *(uint32_t*)&lo;
        v.y = *(uint32_t*)&hi;
        ((uint2*)g_Bbf)[i] = v;
    }
}

// ---------------------------------------------------------------------------
// GEMM1 stream-K: 64 spatial tiles (128x256) x 147 K-iters (BK=64) = 9408
// work units; 147 CTAs x 64 units each (perfect balance, 1 CTA/SM).
// Each CTA spans <=2 tile segments; raw bf16 partials go to slot
// (c - floor(147*t/64)) of 4. relu applied after all slots are summed.
// A read fp32 from z2 (cvt in regs, 2-buf ring); B bf16 cp.async 3-stage.
// 16 warps, warp tile 32x64.
// ---------------------------------------------------------------------------
#define ROWB       144                 // 64 bf16 (128B) + 16B pad
#define A_TILE     (128 * ROWB)        // 18432
#define B_TILE     (256 * ROWB)        // 36864
#define A_OFF      0                   // A ring: 2 x A_TILE
#define B_OFF      (2 * A_TILE)        // B ring: 3 x B_TILE
#define G1_SMEM    (B_OFF + 3 * B_TILE)   // 147456

__global__ __launch_bounds__(512, 1) void gemm1_tc(
    const float* __restrict__ Ag, const __nv_bfloat16* __restrict__ Bg)
{
    extern __shared__ char smem[];
    const uint32_t sb = smem_to_u32(smem);
    const int tid  = threadIdx.x;
    const int lane = tid & 31;
    const int warp = tid >> 5;         // 0..15
    const int wm   = warp >> 2;        // 0..3  (M 32-row strip)
    const int wn   = warp & 3;         // 0..3  (N 64-col strip)
    const int cta  = blockIdx.x;       // 0..146

    const int lrow = lane & 15;
    const int lseg = lane >> 4;

    int t  = (cta * 64) / 147;         // current tile
    int k0 = (cta * 64) % 147;         // starting K-iter within tile
    int remaining = 64;

    float acc[2][8][4];

    #pragma unroll 1
    while (remaining > 0) {
        const int niters = min(remaining, 147 - k0);
        const int mtile = t >> 2, ntile = t & 3;
        const int row0 = mtile * 128;
        const int col0 = ntile * 256;
        const int kbase = k0 * 64;
        const int slot = cta - (147 * t) / 64;

        auto load_B = [&](int buf, int koff) {
            const uint32_t sB = sb + B_OFF + buf * B_TILE;
            #pragma unroll
            for (int i = 0; i < 4; i++) {
                const int v = tid + i * 512;     // 0..2047
                const int r = v >> 3, cc = v & 7;
                CP_ASYNC_16(sB + r * ROWB + cc * 16,
                            Bg + (size_t)(col0 + r) * K1 + koff + cc * 8);
            }
        };
        float4 pre[4];
        auto ldg_A = [&](int koff) {
            #pragma unroll
            for (int i = 0; i < 4; i++) {
                const int v = tid + i * 512;
                const int r = v >> 4, cc = v & 15;
                pre[i] = *(const float4*)(Ag + (size_t)(row0 + r) * K1 + koff + cc * 4);
            }
        };
        auto sts_A = [&](int buf) {
            #pragma unroll
            for (int i = 0; i < 4; i++) {
                const int v = tid + i * 512;
                const int r = v >> 4, cc = v & 15;
                __nv_bfloat162 lo = __floats2bfloat162_rn(pre[i].x, pre[i].y);
                __nv_bfloat162 hi = __floats2bfloat162_rn(pre[i].z, pre[i].w);
                uint2 d;
                d.x = *(uint32_t*)&lo;
                d.y = *(uint32_t*)&hi;
                *(uint2*)(smem + A_OFF + buf * A_TILE + r * ROWB + cc * 8) = d;
            }
        };

        #pragma unroll
        for (int mt = 0; mt < 2; mt++)
            #pragma unroll
            for (int nt = 0; nt < 8; nt++)
                #pragma unroll
                for (int q = 0; q < 4; q++) acc[mt][nt][q] = 0.f;

        // Segment prologue (guard stage-1 loads when niters == 1: OOB)
        ldg_A(kbase);
        load_B(0, kbase);  CP_ASYNC_COMMIT();
        if (niters > 1) load_B(1, kbase + 64);
        CP_ASYNC_COMMIT();
        sts_A(0);
        if (niters > 1) ldg_A(kbase + 64);
        CP_ASYNC_WAIT(1);
        __syncthreads();

        int bbuf = 0;
        #pragma unroll 1
        for (int it = 0; it < niters; it++) {
            const uint32_t sa = sb + A_OFF + (it & 1) * A_TILE;
            const uint32_t sB = sb + B_OFF + bbuf * B_TILE;

            if (it + 2 < niters) {
                int nb = bbuf + 2; if (nb >= 3) nb -= 3;
                load_B(nb, kbase + (it + 2) * 64);
            }
            CP_ASYNC_COMMIT();

            #pragma unroll
            for (int ks = 0; ks < 4; ks++) {
                const uint32_t koff = ks * 32 + lseg * 16;
                uint32_t a[2][4];
                #pragma unroll
                for (int mt = 0; mt < 2; mt++) {
                    uint32_t ad = sa + (uint32_t)(wm * 32 + mt * 16 + lrow) * ROWB + koff;
                    LDSM_X4(a[mt][0], a[mt][1], a[mt][2], a[mt][3], ad);
                }
                uint32_t bfr[4][4];
                #pragma unroll
                for (int nb2 = 0; nb2 < 4; nb2++) {
                    uint32_t bd = sB + (uint32_t)(wn * 64 + nb2 * 16 + lrow) * ROWB + koff;
                    LDSM_X4(bfr[nb2][0], bfr[nb2][1], bfr[nb2][2], bfr[nb2][3], bd);
                }
                #pragma unroll
                for (int mt = 0; mt < 2; mt++)
                    #pragma unroll
                    for (int nt = 0; nt < 8; nt++) {
                        const int nb2 = nt >> 1, rs = nt & 1;
                        MMA_BF16(acc[mt][nt][0], acc[mt][nt][1], acc[mt][nt][2], acc[mt][nt][3],
                                 a[mt][0], a[mt][1], a[mt][2], a[mt][3],
                                 bfr[nb2][rs], bfr[nb2][rs + 2]);
                    }
            }

            if (it + 1 < niters) sts_A((it + 1) & 1);
            if (it + 2 < niters) ldg_A(kbase + (it + 2) * 64);

            CP_ASYNC_WAIT(1);
            __syncthreads();
            bbuf++; if (bbuf >= 3) bbuf = 0;
        }

        // Segment epilogue: raw bf16 partials into this segment's slot.
        // acc regs: [0]=(r,c) [1]=(r,c+1) [2]=(r+8,c) [3]=(r+8,c+1).
        {
            __nv_bfloat16* Dp = g_Dbf + (size_t)slot * BSZ * N1;
            const int rbase = row0 + wm * 32 + (lane >> 2);
            const int cbase = col0 + wn * 64 + (lane & 3) * 2;
            #pragma unroll
            for (int mt = 0; mt < 2; mt++)
                #pragma unroll
                for (int nt = 0; nt < 8; nt++) {
                    const int r = rbase + mt * 16;
                    const int c = cbase + nt * 8;
                    __nv_bfloat162 v0 = __floats2bfloat162_rn(acc[mt][nt][0], acc[mt][nt][1]);
                    __nv_bfloat162 v1 = __floats2bfloat162_rn(acc[mt][nt][2], acc[mt][nt][3]);
                    *(uint32_t*)(Dp + (size_t)r * N1 + c)       = *(uint32_t*)&v0;
                    *(uint32_t*)(Dp + (size_t)(r + 8) * N1 + c) = *(uint32_t*)&v1;
                }
        }

        remaining -= niters;
        t++;
        k0 = 0;
    }
}

// relu(sum of this tile's nseg slots + bias) column sums.
// 512 blocks (128 row-blocks x 4 col-blocks), 256 thr, 16 rows each.
__global__ void relu_colsum_kernel(const float* __restrict__ bias)
{
    const int bm = blockIdx.x & 127;       // 16-row block
    const int bn = blockIdx.x >> 7;        // 256-col block
    const int c  = bn * 256 + threadIdx.x;
    const int t  = ((bm >> 3) << 2) + bn;  // spatial tile id
    const int c_first = (147 * t) / 64;
    const int c_last  = (147 * t + 146) / 64;
    const int nseg = c_last - c_first + 1; // 3 or 4
    const float bb = bias[c];
    const __nv_bfloat16* p = g_Dbf + (size_t)(bm * 16) * N1 + c;
    float s = 0.f;
    #pragma unroll
    for (int r = 0; r < 16; r++) {
        float v = bb;
        for (int sl = 0; sl < nseg; sl++)
            v += __bfloat162float(p[(size_t)sl * BSZ * N1 + (size_t)r * N1]);
        s += fmaxf(v, 0.f);
    }
    g_partial[bm * N1 + c] = s;
}

// g_T[c] = (Σ_m g_partial[m]) . W_fc[c, HD:] + 2048*b_fc[c]
__global__ void s2_kernel(const float* __restrict__ Wfc, const float* __restrict__ bfc)
{
    __shared__ float red[1024];
    const int c = blockIdx.x, tid = threadIdx.x;
    float u = 0.f;
    #pragma unroll 8
    for (int m = 0; m < 128; m++) u += g_partial[m * N1 + tid];
    red[tid] = u * Wfc[(size_t)c * WLD + HD + tid];
    __syncthreads();
    for (int s = 512; s > 0; s >>= 1) {
        if (tid < s) red[tid] += red[tid + s];
        __syncthreads();
    }
    if (tid == 0) g_T[c] = red[0] + 2048.f * bfc[c];
}

// ---------------------------------------------------------------------------
// s1 = z1 @ W_fc[:, :HD]^T, split-K 16 slices of 128.
// ---------------------------------------------------------------------------
__global__ __launch_bounds__(256, 2) void s1_kernel(
    const float* __restrict__ A, const float* __restrict__ W)
{
    __shared__ float As[16][132];
    __shared__ float Bs[16][68];

    const int tid   = threadIdx.x;
    const int cg    = tid & 15;
    const int rg    = tid >> 4;
    const int row0  = blockIdx.x * 128;
    const int kbase = blockIdx.y * 128;

    const int lrow = tid >> 2;
    const int lq   = tid & 3;
    const float* Aptr0 = A + (size_t)(row0 + lrow) * HD + kbase + lq * 4;
    const float* Aptr1 = Aptr0 + (size_t)64 * HD;

    float acc[8][5];
    #pragma unroll
    for (int r = 0; r < 8; r++)
        #pragma unroll
        for (int j = 0; j < 5; j++) acc[r][j] = 0.f;

    for (int kk = 0; kk < 128; kk += 16) {
        __syncthreads();
        {
            float4 a0 = *(const float4*)(Aptr0 + kk);
            float4 a1 = *(const float4*)(Aptr1 + kk);
            As[lq*4+0][lrow]    = a0.x; As[lq*4+1][lrow]    = a0.y;
            As[lq*4+2][lrow]    = a0.z; As[lq*4+3][lrow]    = a0.w;
            As[lq*4+0][lrow+64] = a1.x; As[lq*4+1][lrow+64] = a1.y;
            As[lq*4+2][lrow+64] = a1.z; As[lq*4+3][lrow+64] = a1.w;
        }
        for (int f = tid; f < NC * 4; f += 256) {
            int n = f >> 2, q = f & 3;
            float4 w = *(const float4*)(W + (size_t)n * WLD + kbase + kk + q * 4);
            Bs[q*4+0][n] = w.x; Bs[q*4+1][n] = w.y;
            Bs[q*4+2][n] = w.z; Bs[q*4+3][n] = w.w;
        }
        __syncthreads();

        if (cg < 13) {
            #pragma unroll
            for (int k = 0; k < 16; k++) {
                float4 av0 = *(const float4*)(&As[k][rg*8]);
                float4 av1 = *(const float4*)(&As[k][rg*8+4]);
                float a[8] = {av0.x,av0.y,av0.z,av0.w,av1.x,av1.y,av1.z,av1.w};
                #pragma unroll
                for (int j = 0; j < 5; j++) {
                    float b = Bs[k][cg*5 + j];
                    #pragma unroll
                    for (int r = 0; r < 8; r++)
                        acc[r][j] += a[r] * b;
                }
            }
        }
    }

    if (cg < 13) {
        #pragma unroll
        for (int r = 0; r < 8; r++)
            #pragma unroll
            for (int j = 0; j < 5; j++)
                g_s1part[(size_t)blockIdx.y * (BSZ * NC)
                         + (size_t)(row0 + rg*8 + r) * NC + cg*5 + j] = acc[r][j];
    }
}

// out[i,c] = 2048 * s1[i,c] + g_T[c]
__global__ void out_kernel(float* __restrict__ out)
{
    int idx = blockIdx.x * 256 + threadIdx.x;
    if (idx < BSZ * NC) {
        int c = idx % NC;
        float s = 0.f;
        #pragma unroll
        for (int sl = 0; sl < KSPLIT; sl++) s += g_s1part[sl * (BSZ * NC) + idx];
        out[idx] = 2048.f * s + g_T[c];
    }
}

extern "C" void kernel_launch(void* const* d_in, const int* in_sizes, int n_in,
                              void* d_out, int out_size)
{
    const float* z1  = (const float*)d_in[0];
    const float* z2  = (const float*)d_in[1];
    const float* Wp  = (const float*)d_in[2];
    const float* bp  = (const float*)d_in[3];
    const float* Wfc = (const float*)d_in[4];
    const float* bfc = (const float*)d_in[5];
    float* out = (float*)d_out;

    cudaFuncSetAttribute(gemm1_tc, cudaFuncAttributeMaxDynamicSharedMemorySize, G1_SMEM);

    __nv_bfloat16* Bbf = nullptr;
    cudaGetSymbolAddress((void**)&Bbf, g_Bbf);

    // Side stream + events, created once (no device memory involved).
    static cudaStream_t s_side = nullptr;
    static cudaEvent_t  ev_fork = nullptr, ev_join = nullptr;
    if (s_side == nullptr) {
        cudaStreamCreateWithFlags(&s_side, cudaStreamNonBlocking);
        cudaEventCreateWithFlags(&ev_fork, cudaEventDisableTiming);
        cudaEventCreateWithFlags(&ev_join, cudaEventDisableTiming);
    }

    // Fork: side stream inherits capture via event wait.
    cudaEventRecord(ev_fork, 0);
    cudaStreamWaitEvent(s_side, ev_fork, 0);

    // Side branch: s1 (fp32, SIMT) — overlaps the compute-bound gemm chain.
    s1_kernel<<<dim3(16, KSPLIT), 256, 0, s_side>>>(z1, Wfc);
    cudaEventRecord(ev_join, s_side);

    // Main branch: convert B -> stream-K gemm1 -> relu+colsum -> s2
    convertB_kernel<<<592, 512>>>(Wp);
    gemm1_tc<<<147, 512, G1_SMEM>>>(z2, Bbf);
    relu_colsum_kernel<<<512, 256>>>(bp);
    s2_kernel<<<NC, 1024>>>(Wfc, bfc);

    // Join, then combine.
    cudaStreamWaitEvent(0, ev_join, 0);
    out_kernel<<<(BSZ * NC + 255) / 256, 256>>>(out);
}

// round 15
// speedup vs baseline: 1.0906x; 1.0400x over previous
#include <cuda_runtime.h>
#include <cuda_bf16.h>
#include <cstdint>

// Problem constants
#define BSZ   2048
#define K1    9408     // 3*56*56
#define N1    1024     // PROJ_OUT
#define HD    2048     // HIDDEN_DIM
#define NC    65       // N_CLASSES
#define WLD   3072     // W_fc leading dim
#define KSPLIT 16      // s1 split-K slices

// ---------------------------------------------------------------------------
// PTX helpers (baseline ISA only)
// ---------------------------------------------------------------------------
__device__ __forceinline__ uint32_t smem_to_u32(const void* p) {
    uint32_t a;
    asm("{ .reg .u64 t; cvta.to.shared.u64 t, %1; cvt.u32.u64 %0, t; }" : "=r"(a) : "l"(p));
    return a;
}
#define CP_ASYNC_16(dst, src) \
    asm volatile("cp.async.cg.shared.global [%0], [%1], 16;" :: "r"(dst), "l"(src))
#define CP_ASYNC_COMMIT() asm volatile("cp.async.commit_group;" ::: "memory")
#define CP_ASYNC_WAIT(n)  asm volatile("cp.async.wait_group %0;" :: "n"(n) : "memory")

#define LDSM_X4(r0,r1,r2,r3,addr) \
    asm volatile("ldmatrix.sync.aligned.m8n8.x4.shared.b16 {%0,%1,%2,%3}, [%4];" \
        : "=r"(r0),"=r"(r1),"=r"(r2),"=r"(r3) : "r"(addr))

#define MMA_BF16(c0,c1,c2,c3,a0,a1,a2,a3,b0,b1) \
    asm volatile("mma.sync.aligned.m16n8k16.row.col.f32.bf16.bf16.f32 " \
        "{%0,%1,%2,%3}, {%4,%5,%6,%7}, {%8,%9}, {%0,%1,%2,%3};" \
        : "+f"(c0),"+f"(c1),"+f"(c2),"+f"(c3) \
        : "r"(a0),"r"(a1),"r"(a2),"r"(a3), "r"(b0),"r"(b1))

// ---------------------------------------------------------------------------
// Scratch
// ---------------------------------------------------------------------------
__device__ __nv_bfloat16 g_Bbf[(size_t)N1 * K1];      // W_proj bf16 (19.3 MB)
__device__ __nv_bfloat16 g_Dbf[(size_t)4 * BSZ * N1]; // stream-K partial slots (16.8 MB)
__device__ float g_partial[128 * N1];                 // per row-block column sums
__device__ float g_T[NC];
__device__ float g_s1part[KSPLIT * BSZ * NC];

// ---------------------------------------------------------------------------
// fp32 -> bf16 conversion for B (W_proj).
// ---------------------------------------------------------------------------
#define NB4 ((N1 * K1) / 4)
__global__ void convertB_kernel(const float* __restrict__ srcB)
{
    int i = blockIdx.x * blockDim.x + threadIdx.x;
    const int stride = gridDim.x * blockDim.x;
    for (; i < NB4; i += stride) {
        float4 f = ((const float4*)srcB)[i];
        __nv_bfloat162 lo = __floats2bfloat162_rn(f.x, f.y);
        __nv_bfloat162 hi = __floats2bfloat162_rn(f.z, f.w);
        uint2 v;
        v.x = *(uint32_t*)&lo;
        v.y = *(uint32_t*)&hi;
        ((uint2*)g_Bbf)[i] = v;
    }
}

// ---------------------------------------------------------------------------
// GEMM1 stream-K: 64 spatial tiles (128x256) x 147 K-iters (BK=64) = 9408
// work units; 147 CTAs x 64 units each (perfect balance, 1 CTA/SM).
// Raw bf16 partials to slot (cta - floor(147*t/64)); relu after slot sum.
// ---------------------------------------------------------------------------
#define ROWB       144                 // 64 bf16 (128B) + 16B pad
#define A_TILE     (128 * ROWB)        // 18432
#define B_TILE     (256 * ROWB)        // 36864
#define A_OFF      0                   // A ring: 2 x A_TILE
#define B_OFF      (2 * A_TILE)        // B ring: 3 x B_TILE
#define G1_SMEM    (B_OFF + 3 * B_TILE)   // 147456

__global__ __launch_bounds__(512, 1) void gemm1_tc(
    const float* __restrict__ Ag, const __nv_bfloat16* __restrict__ Bg)
{
    extern __shared__ char smem[];
    const uint32_t sb = smem_to_u32(smem);
    const int tid  = threadIdx.x;
    const int lane = tid & 31;
    const int warp = tid >> 5;         // 0..15
    const int wm   = warp >> 2;        // 0..3  (M 32-row strip)
    const int wn   = warp & 3;         // 0..3  (N 64-col strip)
    const int cta  = blockIdx.x;       // 0..146

    const int lrow = lane & 15;
    const int lseg = lane >> 4;

    int t  = (cta * 64) / 147;         // current tile
    int k0 = (cta * 64) % 147;         // starting K-iter within tile
    int remaining = 64;

    float acc[2][8][4];

    #pragma unroll 1
    while (remaining > 0) {
        const int niters = min(remaining, 147 - k0);
        const int mtile = t >> 2, ntile = t & 3;
        const int row0 = mtile * 128;
        const int col0 = ntile * 256;
        const int kbase = k0 * 64;
        const int slot = cta - (147 * t) / 64;

        auto load_B = [&](int buf, int koff) {
            const uint32_t sB = sb + B_OFF + buf * B_TILE;
            #pragma unroll
            for (int i = 0; i < 4; i++) {
                const int v = tid + i * 512;     // 0..2047
                const int r = v >> 3, cc = v & 7;
                CP_ASYNC_16(sB + r * ROWB + cc * 16,
                            Bg + (size_t)(col0 + r) * K1 + koff + cc * 8);
            }
        };
        float4 pre[4];
        auto ldg_A = [&](int koff) {
            #pragma unroll
            for (int i = 0; i < 4; i++) {
                const int v = tid + i * 512;
                const int r = v >> 4, cc = v & 15;
                pre[i] = *(const float4*)(Ag + (size_t)(row0 + r) * K1 + koff + cc * 4);
            }
        };
        auto sts_A = [&](int buf) {
            #pragma unroll
            for (int i = 0; i < 4; i++) {
                const int v = tid + i * 512;
                const int r = v >> 4, cc = v & 15;
                __nv_bfloat162 lo = __floats2bfloat162_rn(pre[i].x, pre[i].y);
                __nv_bfloat162 hi = __floats2bfloat162_rn(pre[i].z, pre[i].w);
                uint2 d;
                d.x = *(uint32_t*)&lo;
                d.y = *(uint32_t*)&hi;
                *(uint2*)(smem + A_OFF + buf * A_TILE + r * ROWB + cc * 8) = d;
            }
        };

        #pragma unroll
        for (int mt = 0; mt < 2; mt++)
            #pragma unroll
            for (int nt = 0; nt < 8; nt++)
                #pragma unroll
                for (int q = 0; q < 4; q++) acc[mt][nt][q] = 0.f;

        // Segment prologue (guard stage-1 loads when niters == 1: OOB)
        ldg_A(kbase);
        load_B(0, kbase);  CP_ASYNC_COMMIT();
        if (niters > 1) load_B(1, kbase + 64);
        CP_ASYNC_COMMIT();
        sts_A(0);
        if (niters > 1) ldg_A(kbase + 64);
        CP_ASYNC_WAIT(1);
        __syncthreads();

        int bbuf = 0;
        #pragma unroll 1
        for (int it = 0; it < niters; it++) {
            const uint32_t sa = sb + A_OFF + (it & 1) * A_TILE;
            const uint32_t sB = sb + B_OFF + bbuf * B_TILE;

            if (it + 2 < niters) {
                int nb = bbuf + 2; if (nb >= 3) nb -= 3;
                load_B(nb, kbase + (it + 2) * 64);
            }
            CP_ASYNC_COMMIT();

            #pragma unroll
            for (int ks = 0; ks < 4; ks++) {
                const uint32_t koff = ks * 32 + lseg * 16;
                uint32_t a[2][4];
                #pragma unroll
                for (int mt = 0; mt < 2; mt++) {
                    uint32_t ad = sa + (uint32_t)(wm * 32 + mt * 16 + lrow) * ROWB + koff;
                    LDSM_X4(a[mt][0], a[mt][1], a[mt][2], a[mt][3], ad);
                }
                uint32_t bfr[4][4];
                #pragma unroll
                for (int nb2 = 0; nb2 < 4; nb2++) {
                    uint32_t bd = sB + (uint32_t)(wn * 64 + nb2 * 16 + lrow) * ROWB + koff;
                    LDSM_X4(bfr[nb2][0], bfr[nb2][1], bfr[nb2][2], bfr[nb2][3], bd);
                }
                #pragma unroll
                for (int mt = 0; mt < 2; mt++)
                    #pragma unroll
                    for (int nt = 0; nt < 8; nt++) {
                        const int nb2 = nt >> 1, rs = nt & 1;
                        MMA_BF16(acc[mt][nt][0], acc[mt][nt][1], acc[mt][nt][2], acc[mt][nt][3],
                                 a[mt][0], a[mt][1], a[mt][2], a[mt][3],
                                 bfr[nb2][rs], bfr[nb2][rs + 2]);
                    }
            }

            if (it + 1 < niters) sts_A((it + 1) & 1);
            if (it + 2 < niters) ldg_A(kbase + (it + 2) * 64);

            CP_ASYNC_WAIT(1);
            __syncthreads();
            bbuf++; if (bbuf >= 3) bbuf = 0;
        }

        // Segment epilogue: raw bf16 partials into this segment's slot.
        {
            __nv_bfloat16* Dp = g_Dbf + (size_t)slot * BSZ * N1;
            const int rbase = row0 + wm * 32 + (lane >> 2);
            const int cbase = col0 + wn * 64 + (lane & 3) * 2;
            #pragma unroll
            for (int mt = 0; mt < 2; mt++)
                #pragma unroll
                for (int nt = 0; nt < 8; nt++) {
                    const int r = rbase + mt * 16;
                    const int c = cbase + nt * 8;
                    __nv_bfloat162 v0 = __floats2bfloat162_rn(acc[mt][nt][0], acc[mt][nt][1]);
                    __nv_bfloat162 v1 = __floats2bfloat162_rn(acc[mt][nt][2], acc[mt][nt][3]);
                    *(uint32_t*)(Dp + (size_t)r * N1 + c)       = *(uint32_t*)&v0;
                    *(uint32_t*)(Dp + (size_t)(r + 8) * N1 + c) = *(uint32_t*)&v1;
                }
        }

        remaining -= niters;
        t++;
        k0 = 0;
    }
}

// relu(sum of this tile's nseg slots + bias) column sums.
// nseg is 3 or 4 -> branch once into fully-unrolled paths (MLP-rich loads).
__global__ void relu_colsum_kernel(const float* __restrict__ bias)
{
    const int bm = blockIdx.x & 127;       // 16-row block
    const int bn = blockIdx.x >> 7;        // 256-col block
    const int c  = bn * 256 + threadIdx.x;
    const int t  = ((bm >> 3) << 2) + bn;  // spatial tile id
    const int c_first = (147 * t) / 64;
    const int c_last  = (147 * t + 146) / 64;
    const int nseg = c_last - c_first + 1; // 3 or 4
    const float bb = bias[c];
    const __nv_bfloat16* p = g_Dbf + (size_t)(bm * 16) * N1 + c;

    float v[16];
    #pragma unroll
    for (int r = 0; r < 16; r++) v[r] = bb;

    if (nseg == 4) {
        #pragma unroll
        for (int sl = 0; sl < 4; sl++) {
            const __nv_bfloat16* ps = p + (size_t)sl * BSZ * N1;
            #pragma unroll
            for (int r = 0; r < 16; r++)
                v[r] += __bfloat162float(ps[(size_t)r * N1]);
        }
    } else {
        #pragma unroll
        for (int sl = 0; sl < 3; sl++) {
            const __nv_bfloat16* ps = p + (size_t)sl * BSZ * N1;
            #pragma unroll
            for (int r = 0; r < 16; r++)
                v[r] += __bfloat162float(ps[(size_t)r * N1]);
        }
    }

    float s = 0.f;
    #pragma unroll
    for (int r = 0; r < 16; r++) s += fmaxf(v[r], 0.f);
    g_partial[bm * N1 + c] = s;
}

// g_T[c] = (Σ_m g_partial[m]) . W_fc[c, HD:] + 2048*b_fc[c]
__global__ void s2_kernel(const float* __restrict__ Wfc, const float* __restrict__ bfc)
{
    __shared__ float red[1024];
    const int c = blockIdx.x, tid = threadIdx.x;
    float u = 0.f;
    #pragma unroll 8
    for (int m = 0; m < 128; m++) u += g_partial[m * N1 + tid];
    red[tid] = u * Wfc[(size_t)c * WLD + HD + tid];
    __syncthreads();
    for (int s = 512; s > 0; s >>= 1) {
        if (tid < s) red[tid] += red[tid + s];
        __syncthreads();
    }
    if (tid == 0) g_T[c] = red[0] + 2048.f * bfc[c];
}

// ---------------------------------------------------------------------------
// s1 = z1 @ W_fc[:, :HD]^T, split-K 16 slices of 128.
// ---------------------------------------------------------------------------
__global__ __launch_bounds__(256, 2) void s1_kernel(
    const float* __restrict__ A, const float* __restrict__ W)
{
    __shared__ float As[16][132];
    __shared__ float Bs[16][68];

    const int tid   = threadIdx.x;
    const int cg    = tid & 15;
    const int rg    = tid >> 4;
    const int row0  = blockIdx.x * 128;
    const int kbase = blockIdx.y * 128;

    const int lrow = tid >> 2;
    const int lq   = tid & 3;
    const float* Aptr0 = A + (size_t)(row0 + lrow) * HD + kbase + lq * 4;
    const float* Aptr1 = Aptr0 + (size_t)64 * HD;

    float acc[8][5];
    #pragma unroll
    for (int r = 0; r < 8; r++)
        #pragma unroll
        for (int j = 0; j < 5; j++) acc[r][j] = 0.f;

    for (int kk = 0; kk < 128; kk += 16) {
        __syncthreads();
        {
            float4 a0 = *(const float4*)(Aptr0 + kk);
            float4 a1 = *(const float4*)(Aptr1 + kk);
            As[lq*4+0][lrow]    = a0.x; As[lq*4+1][lrow]    = a0.y;
            As[lq*4+2][lrow]    = a0.z; As[lq*4+3][lrow]    = a0.w;
            As[lq*4+0][lrow+64] = a1.x; As[lq*4+1][lrow+64] = a1.y;
            As[lq*4+2][lrow+64] = a1.z; As[lq*4+3][lrow+64] = a1.w;
        }
        for (int f = tid; f < NC * 4; f += 256) {
            int n = f >> 2, q = f & 3;
            float4 w = *(const float4*)(W + (size_t)n * WLD + kbase + kk + q * 4);
            Bs[q*4+0][n] = w.x; Bs[q*4+1][n] = w.y;
            Bs[q*4+2][n] = w.z; Bs[q*4+3][n] = w.w;
        }
        __syncthreads();

        if (cg < 13) {
            #pragma unroll
            for (int k = 0; k < 16; k++) {
                float4 av0 = *(const float4*)(&As[k][rg*8]);
                float4 av1 = *(const float4*)(&As[k][rg*8+4]);
                float a[8] = {av0.x,av0.y,av0.z,av0.w,av1.x,av1.y,av1.z,av1.w};
                #pragma unroll
                for (int j = 0; j < 5; j++) {
                    float b = Bs[k][cg*5 + j];
                    #pragma unroll
                    for (int r = 0; r < 8; r++)
                        acc[r][j] += a[r] * b;
                }
            }
        }
    }

    if (cg < 13) {
        #pragma unroll
        for (int r = 0; r < 8; r++)
            #pragma unroll
            for (int j = 0; j < 5; j++)
                g_s1part[(size_t)blockIdx.y * (BSZ * NC)
                         + (size_t)(row0 + rg*8 + r) * NC + cg*5 + j] = acc[r][j];
    }
}

// out[i,c] = 2048 * s1[i,c] + g_T[c]
__global__ void out_kernel(float* __restrict__ out)
{
    int idx = blockIdx.x * 256 + threadIdx.x;
    if (idx < BSZ * NC) {
        int c = idx % NC;
        float s = 0.f;
        #pragma unroll
        for (int sl = 0; sl < KSPLIT; sl++) s += g_s1part[sl * (BSZ * NC) + idx];
        out[idx] = 2048.f * s + g_T[c];
    }
}

extern "C" void kernel_launch(void* const* d_in, const int* in_sizes, int n_in,
                              void* d_out, int out_size)
{
    const float* z1  = (const float*)d_in[0];
    const float* z2  = (const float*)d_in[1];
    const float* Wp  = (const float*)d_in[2];
    const float* bp  = (const float*)d_in[3];
    const float* Wfc = (const float*)d_in[4];
    const float* bfc = (const float*)d_in[5];
    float* out = (float*)d_out;

    cudaFuncSetAttribute(gemm1_tc, cudaFuncAttributeMaxDynamicSharedMemorySize, G1_SMEM);

    __nv_bfloat16* Bbf = nullptr;
    cudaGetSymbolAddress((void**)&Bbf, g_Bbf);

    // Side stream + events, created once (no device memory involved).
    static cudaStream_t s_side = nullptr;
    static cudaEvent_t  ev_fork = nullptr, ev_join = nullptr;
    if (s_side == nullptr) {
        cudaStreamCreateWithFlags(&s_side, cudaStreamNonBlocking);
        cudaEventCreateWithFlags(&ev_fork, cudaEventDisableTiming);
        cudaEventCreateWithFlags(&ev_join, cudaEventDisableTiming);
    }

    // Fork: side stream inherits capture via event wait.
    cudaEventRecord(ev_fork, 0);
    cudaStreamWaitEvent(s_side, ev_fork, 0);

    // Side branch: s1 (fp32, SIMT) — overlaps the compute-bound gemm chain.
    s1_kernel<<<dim3(16, KSPLIT), 256, 0, s_side>>>(z1, Wfc);
    cudaEventRecord(ev_join, s_side);

    // Main branch: convert B -> stream-K gemm1 -> relu+colsum -> s2
    convertB_kernel<<<592, 512>>>(Wp);
    gemm1_tc<<<147, 512, G1_SMEM>>>(z2, Bbf);
    relu_colsum_kernel<<<512, 256>>>(bp);
    s2_kernel<<<NC, 1024>>>(Wfc, bfc);

    // Join, then combine.
    cudaStreamWaitEvent(0, ev_join, 0);
    out_kernel<<<(BSZ * NC + 255) / 256, 256>>>(out);
}

// round 16
// speedup vs baseline: 1.1044x; 1.0126x over previous
#include <cuda_runtime.h>
#include <cuda_bf16.h>
#include <cstdint>

// Problem constants
#define BSZ   2048
#define K1    9408     // 3*56*56
#define N1    1024     // PROJ_OUT
#define HD    2048     // HIDDEN_DIM
#define NC    65       // N_CLASSES
#define WLD   3072     // W_fc leading dim
#define KSPLIT 16      // s1 split-K slices

// ---------------------------------------------------------------------------
// PTX helpers (baseline ISA only)
// ---------------------------------------------------------------------------
__device__ __forceinline__ uint32_t smem_to_u32(const void* p) {
    uint32_t a;
    asm("{ .reg .u64 t; cvta.to.shared.u64 t, %1; cvt.u32.u64 %0, t; }" : "=r"(a) : "l"(p));
    return a;
}
#define CP_ASYNC_16(dst, src) \
    asm volatile("cp.async.cg.shared.global [%0], [%1], 16;" :: "r"(dst), "l"(src))
#define CP_ASYNC_COMMIT() asm volatile("cp.async.commit_group;" ::: "memory")
#define CP_ASYNC_WAIT(n)  asm volatile("cp.async.wait_group %0;" :: "n"(n) : "memory")

#define LDSM_X4(r0,r1,r2,r3,addr) \
    asm volatile("ldmatrix.sync.aligned.m8n8.x4.shared.b16 {%0,%1,%2,%3}, [%4];" \
        : "=r"(r0),"=r"(r1),"=r"(r2),"=r"(r3) : "r"(addr))

#define MMA_BF16(c0,c1,c2,c3,a0,a1,a2,a3,b0,b1) \
    asm volatile("mma.sync.aligned.m16n8k16.row.col.f32.bf16.bf16.f32 " \
        "{%0,%1,%2,%3}, {%4,%5,%6,%7}, {%8,%9}, {%0,%1,%2,%3};" \
        : "+f"(c0),"+f"(c1),"+f"(c2),"+f"(c3) \
        : "r"(a0),"r"(a1),"r"(a2),"r"(a3), "r"(b0),"r"(b1))

// ---------------------------------------------------------------------------
// Scratch
// ---------------------------------------------------------------------------
__device__ __nv_bfloat16 g_Bbf[(size_t)N1 * K1];      // W_proj bf16 (19.3 MB)
__device__ __nv_bfloat16 g_Dbf[(size_t)4 * BSZ * N1]; // stream-K partial slots (16.8 MB)
__device__ int   g_flag[64];                          // per-tile segment arrival counters
__device__ float g_partial[32 * N1];                  // per 64-row-block column sums
__device__ float g_T[NC];
__device__ float g_s1part[KSPLIT * BSZ * NC];

// ---------------------------------------------------------------------------
// fp32 -> bf16 conversion for B (W_proj). Also zeroes the stream-K flags
// (runs before gemm1 in stream order every launch/replay).
// ---------------------------------------------------------------------------
#define NB4 ((N1 * K1) / 4)
__global__ void convertB_kernel(const float* __restrict__ srcB)
{
    if (blockIdx.x == 0 && threadIdx.x < 64) g_flag[threadIdx.x] = 0;
    int i = blockIdx.x * blockDim.x + threadIdx.x;
    const int stride = gridDim.x * blockDim.x;
    for (; i < NB4; i += stride) {
        float4 f = ((const float4*)srcB)[i];
        __nv_bfloat162 lo = __floats2bfloat162_rn(f.x, f.y);
        __nv_bfloat162 hi = __floats2bfloat162_rn(f.z, f.w);
        uint2 v;
        v.x = *(uint32_t*)&lo;
        v.y = *(uint32_t*)&hi;
        ((uint2*)g_Bbf)[i] = v;
    }
}

// Fixup helper: relu(sum of NSEG slots + bias) summed over 64 rows of one column.
template<int NSEG>
__device__ __forceinline__ float fix_sum(const __nv_bfloat16* p, float bb)
{
    float s = 0.f;
    #pragma unroll 8
    for (int r = 0; r < 64; r++) {
        float v = bb;
        #pragma unroll
        for (int sl = 0; sl < NSEG; sl++)
            v += __bfloat162float(p[(size_t)sl * ((size_t)BSZ * N1) + (size_t)r * N1]);
        s += fmaxf(v, 0.f);
    }
    return s;
}

// ---------------------------------------------------------------------------
// GEMM1 stream-K + in-kernel fixup: 64 spatial tiles (128x256) x 147 K-iters
// = 9408 units; 147 CTAs x 64 units (perfect balance, 1 CTA/SM).
// Raw bf16 partials -> slot (cta - floor(147t/64)). The LAST segment CTA of
// each tile (atomic counter) sums slots + bias, applies relu, column-sums
// over the tile's 128 rows, and writes g_partial — no separate kernel.
// ---------------------------------------------------------------------------
#define ROWB       144                 // 64 bf16 (128B) + 16B pad
#define A_TILE     (128 * ROWB)        // 18432
#define B_TILE     (256 * ROWB)        // 36864
#define A_OFF      0                   // A ring: 2 x A_TILE
#define B_OFF      (2 * A_TILE)        // B ring: 3 x B_TILE
#define FIX_OFF    (B_OFF + 3 * B_TILE)
#define G1_SMEM    (FIX_OFF + 16)

__global__ __launch_bounds__(512, 1) void gemm1_tc(
    const float* __restrict__ Ag, const __nv_bfloat16* __restrict__ Bg,
    const float* __restrict__ bias)
{
    extern __shared__ char smem[];
    const uint32_t sb = smem_to_u32(smem);
    const int tid  = threadIdx.x;
    const int lane = tid & 31;
    const int warp = tid >> 5;         // 0..15
    const int wm   = warp >> 2;        // 0..3  (M 32-row strip)
    const int wn   = warp & 3;         // 0..3  (N 64-col strip)
    const int cta  = blockIdx.x;       // 0..146

    const int lrow = lane & 15;
    const int lseg = lane >> 4;
    volatile int* fixflag = (volatile int*)(smem + FIX_OFF);

    int t  = (cta * 64) / 147;         // current tile
    int k0 = (cta * 64) % 147;         // starting K-iter within tile
    int remaining = 64;

    float acc[2][8][4];

    #pragma unroll 1
    while (remaining > 0) {
        const int niters = min(remaining, 147 - k0);
        const int mtile = t >> 2, ntile = t & 3;
        const int row0 = mtile * 128;
        const int col0 = ntile * 256;
        const int kbase = k0 * 64;
        const int c_first = (147 * t) / 64;
        const int c_last  = (147 * t + 146) / 64;
        const int nseg = c_last - c_first + 1;   // 3 or 4
        const int slot = cta - c_first;

        auto load_B = [&](int buf, int koff) {
            const uint32_t sB = sb + B_OFF + buf * B_TILE;
            #pragma unroll
            for (int i = 0; i < 4; i++) {
                const int v = tid + i * 512;     // 0..2047
                const int r = v >> 3, cc = v & 7;
                CP_ASYNC_16(sB + r * ROWB + cc * 16,
                            Bg + (size_t)(col0 + r) * K1 + koff + cc * 8);
            }
        };
        float4 pre[4];
        auto ldg_A = [&](int koff) {
            #pragma unroll
            for (int i = 0; i < 4; i++) {
                const int v = tid + i * 512;
                const int r = v >> 4, cc = v & 15;
                pre[i] = *(const float4*)(Ag + (size_t)(row0 + r) * K1 + koff + cc * 4);
            }
        };
        auto sts_A = [&](int buf) {
            #pragma unroll
            for (int i = 0; i < 4; i++) {
                const int v = tid + i * 512;
                const int r = v >> 4, cc = v & 15;
                __nv_bfloat162 lo = __floats2bfloat162_rn(pre[i].x, pre[i].y);
                __nv_bfloat162 hi = __floats2bfloat162_rn(pre[i].z, pre[i].w);
                uint2 d;
                d.x = *(uint32_t*)&lo;
                d.y = *(uint32_t*)&hi;
                *(uint2*)(smem + A_OFF + buf * A_TILE + r * ROWB + cc * 8) = d;
            }
        };

        #pragma unroll
        for (int mt = 0; mt < 2; mt++)
            #pragma unroll
            for (int nt = 0; nt < 8; nt++)
                #pragma unroll
                for (int q = 0; q < 4; q++) acc[mt][nt][q] = 0.f;

        // Segment prologue (guard stage-1 loads when niters == 1: OOB)
        ldg_A(kbase);
        load_B(0, kbase);  CP_ASYNC_COMMIT();
        if (niters > 1) load_B(1, kbase + 64);
        CP_ASYNC_COMMIT();
        sts_A(0);
        if (niters > 1) ldg_A(kbase + 64);
        CP_ASYNC_WAIT(1);
        __syncthreads();

        int bbuf = 0;
        #pragma unroll 1
        for (int it = 0; it < niters; it++) {
            const uint32_t sa = sb + A_OFF + (it & 1) * A_TILE;
            const uint32_t sB = sb + B_OFF + bbuf * B_TILE;

            if (it + 2 < niters) {
                int nb = bbuf + 2; if (nb >= 3) nb -= 3;
                load_B(nb, kbase + (it + 2) * 64);
            }
            CP_ASYNC_COMMIT();

            #pragma unroll
            for (int ks = 0; ks < 4; ks++) {
                const uint32_t koff = ks * 32 + lseg * 16;
                uint32_t a[2][4];
                #pragma unroll
                for (int mt = 0; mt < 2; mt++) {
                    uint32_t ad = sa + (uint32_t)(wm * 32 + mt * 16 + lrow) * ROWB + koff;
                    LDSM_X4(a[mt][0], a[mt][1], a[mt][2], a[mt][3], ad);
                }
                uint32_t bfr[4][4];
                #pragma unroll
                for (int nb2 = 0; nb2 < 4; nb2++) {
                    uint32_t bd = sB + (uint32_t)(wn * 64 + nb2 * 16 + lrow) * ROWB + koff;
                    LDSM_X4(bfr[nb2][0], bfr[nb2][1], bfr[nb2][2], bfr[nb2][3], bd);
                }
                #pragma unroll
                for (int mt = 0; mt < 2; mt++)
                    #pragma unroll
                    for (int nt = 0; nt < 8; nt++) {
                        const int nb2 = nt >> 1, rs = nt & 1;
                        MMA_BF16(acc[mt][nt][0], acc[mt][nt][1], acc[mt][nt][2], acc[mt][nt][3],
                                 a[mt][0], a[mt][1], a[mt][2], a[mt][3],
                                 bfr[nb2][rs], bfr[nb2][rs + 2]);
                    }
            }

            if (it + 1 < niters) sts_A((it + 1) & 1);
            if (it + 2 < niters) ldg_A(kbase + (it + 2) * 64);

            CP_ASYNC_WAIT(1);
            __syncthreads();
            bbuf++; if (bbuf >= 3) bbuf = 0;
        }

        // Segment epilogue: raw bf16 partials into this segment's slot.
        {
            __nv_bfloat16* Dp = g_Dbf + (size_t)slot * BSZ * N1;
            const int rbase = row0 + wm * 32 + (lane >> 2);
            const int cbase = col0 + wn * 64 + (lane & 3) * 2;
            #pragma unroll
            for (int mt = 0; mt < 2; mt++)
                #pragma unroll
                for (int nt = 0; nt < 8; nt++) {
                    const int r = rbase + mt * 16;
                    const int c = cbase + nt * 8;
                    __nv_bfloat162 v0 = __floats2bfloat162_rn(acc[mt][nt][0], acc[mt][nt][1]);
                    __nv_bfloat162 v1 = __floats2bfloat162_rn(acc[mt][nt][2], acc[mt][nt][3]);
                    *(uint32_t*)(Dp + (size_t)r * N1 + c)       = *(uint32_t*)&v0;
                    *(uint32_t*)(Dp + (size_t)(r + 8) * N1 + c) = *(uint32_t*)&v1;
                }
        }

        // Stream-K fixup: last-arriving segment CTA finalizes this tile.
        __threadfence();
        __syncthreads();            // all threads' stores + fences done
        if (tid == 0) {
            int old = atomicAdd(&g_flag[t], 1);
            *fixflag = (old == nseg - 1) ? 1 : 0;
            __threadfence();        // acquire: later reads see all slots
        }
        __syncthreads();
        if (*fixflag) {
            const int col  = tid & 255;
            const int half = tid >> 8;
            const int c    = col0 + col;
            const float bb = bias[c];
            const __nv_bfloat16* p = g_Dbf + (size_t)(row0 + half * 64) * N1 + c;
            float s;
            if (nseg == 4)      s = fix_sum<4>(p, bb);
            else if (nseg == 3) s = fix_sum<3>(p, bb);
            else                s = fix_sum<2>(p, bb);
            g_partial[((mtile << 1) + half) * N1 + c] = s;
        }

        remaining -= niters;
        t++;
        k0 = 0;
    }
}

// g_T[c] = (Σ_m g_partial[m]) . W_fc[c, HD:] + 2048*b_fc[c]
__global__ void s2_kernel(const float* __restrict__ Wfc, const float* __restrict__ bfc)
{
    __shared__ float red[1024];
    const int c = blockIdx.x, tid = threadIdx.x;
    float u = 0.f;
    #pragma unroll
    for (int m = 0; m < 32; m++) u += g_partial[m * N1 + tid];
    red[tid] = u * Wfc[(size_t)c * WLD + HD + tid];
    __syncthreads();
    for (int s = 512; s > 0; s >>= 1) {
        if (tid < s) red[tid] += red[tid + s];
        __syncthreads();
    }
    if (tid == 0) g_T[c] = red[0] + 2048.f * bfc[c];
}

// ---------------------------------------------------------------------------
// s1 = z1 @ W_fc[:, :HD]^T, split-K 16 slices of 128.
// ---------------------------------------------------------------------------
__global__ __launch_bounds__(256, 2) void s1_kernel(
    const float* __restrict__ A, const float* __restrict__ W)
{
    __shared__ float As[16][132];
    __shared__ float Bs[16][68];

    const int tid   = threadIdx.x;
    const int cg    = tid & 15;
    const int rg    = tid >> 4;
    const int row0  = blockIdx.x * 128;
    const int kbase = blockIdx.y * 128;

    const int lrow = tid >> 2;
    const int lq   = tid & 3;
    const float* Aptr0 = A + (size_t)(row0 + lrow) * HD + kbase + lq * 4;
    const float* Aptr1 = Aptr0 + (size_t)64 * HD;

    float acc[8][5];
    #pragma unroll
    for (int r = 0; r < 8; r++)
        #pragma unroll
        for (int j = 0; j < 5; j++) acc[r][j] = 0.f;

    for (int kk = 0; kk < 128; kk += 16) {
        __syncthreads();
        {
            float4 a0 = *(const float4*)(Aptr0 + kk);
            float4 a1 = *(const float4*)(Aptr1 + kk);
            As[lq*4+0][lrow]    = a0.x; As[lq*4+1][lrow]    = a0.y;
            As[lq*4+2][lrow]    = a0.z; As[lq*4+3][lrow]    = a0.w;
            As[lq*4+0][lrow+64] = a1.x; As[lq*4+1][lrow+64] = a1.y;
            As[lq*4+2][lrow+64] = a1.z; As[lq*4+3][lrow+64] = a1.w;
        }
        for (int f = tid; f < NC * 4; f += 256) {
            int n = f >> 2, q = f & 3;
            float4 w = *(const float4*)(W + (size_t)n * WLD + kbase + kk + q * 4);
            Bs[q*4+0][n] = w.x; Bs[q*4+1][n] = w.y;
            Bs[q*4+2][n] = w.z; Bs[q*4+3][n] = w.w;
        }
        __syncthreads();

        if (cg < 13) {
            #pragma unroll
            for (int k = 0; k < 16; k++) {
                float4 av0 = *(const float4*)(&As[k][rg*8]);
                float4 av1 = *(const float4*)(&As[k][rg*8+4]);
                float a[8] = {av0.x,av0.y,av0.z,av0.w,av1.x,av1.y,av1.z,av1.w};
                #pragma unroll
                for (int j = 0; j < 5; j++) {
                    float b = Bs[k][cg*5 + j];
                    #pragma unroll
                    for (int r = 0; r < 8; r++)
                        acc[r][j] += a[r] * b;
                }
            }
        }
    }

    if (cg < 13) {
        #pragma unroll
        for (int r = 0; r < 8; r++)
            #pragma unroll
            for (int j = 0; j < 5; j++)
                g_s1part[(size_t)blockIdx.y * (BSZ * NC)
                         + (size_t)(row0 + rg*8 + r) * NC + cg*5 + j] = acc[r][j];
    }
}

// out[i,c] = 2048 * s1[i,c] + g_T[c]
__global__ void out_kernel(float* __restrict__ out)
{
    int idx = blockIdx.x * 256 + threadIdx.x;
    if (idx < BSZ * NC) {
        int c = idx % NC;
        float s = 0.f;
        #pragma unroll
        for (int sl = 0; sl < KSPLIT; sl++) s += g_s1part[sl * (BSZ * NC) + idx];
        out[idx] = 2048.f * s + g_T[c];
    }
}

extern "C" void kernel_launch(void* const* d_in, const int* in_sizes, int n_in,
                              void* d_out, int out_size)
{
    const float* z1  = (const float*)d_in[0];
    const float* z2  = (const float*)d_in[1];
    const float* Wp  = (const float*)d_in[2];
    const float* bp  = (const float*)d_in[3];
    const float* Wfc = (const float*)d_in[4];
    const float* bfc = (const float*)d_in[5];
    float* out = (float*)d_out;

    cudaFuncSetAttribute(gemm1_tc, cudaFuncAttributeMaxDynamicSharedMemorySize, G1_SMEM);

    __nv_bfloat16* Bbf = nullptr;
    cudaGetSymbolAddress((void**)&Bbf, g_Bbf);

    // Side stream + events, created once (no device memory involved).
    static cudaStream_t s_side = nullptr;
    static cudaEvent_t  ev_fork = nullptr, ev_join = nullptr;
    if (s_side == nullptr) {
        cudaStreamCreateWithFlags(&s_side, cudaStreamNonBlocking);
        cudaEventCreateWithFlags(&ev_fork, cudaEventDisableTiming);
        cudaEventCreateWithFlags(&ev_join, cudaEventDisableTiming);
    }

    // Fork: side stream inherits capture via event wait.
    cudaEventRecord(ev_fork, 0);
    cudaStreamWaitEvent(s_side, ev_fork, 0);

    // Side branch: s1 (fp32, SIMT) — overlaps the compute-bound gemm chain.
    s1_kernel<<<dim3(16, KSPLIT), 256, 0, s_side>>>(z1, Wfc);
    cudaEventRecord(ev_join, s_side);

    // Main branch: convert B (+flag zero) -> stream-K gemm1 (fixup inside) -> s2
    convertB_kernel<<<592, 512>>>(Wp);
    gemm1_tc<<<147, 512, G1_SMEM>>>(z2, Bbf, bp);
    s2_kernel<<<NC, 1024>>>(Wfc, bfc);

    // Join, then combine.
    cudaStreamWaitEvent(0, ev_join, 0);
    out_kernel<<<(BSZ * NC + 255) / 256, 256>>>(out);
}